// round 13
// baseline (speedup 1.0000x reference)
#include <cuda_runtime.h>
#include <cuda_fp16.h>
#include <math.h>
#include <stdint.h>

#define BATCH 4
#define LSEQ 2048
#define DMODEL 1024
#define NHEADS 8
#define DHEAD 128
#define MROWS (BATCH*LSEQ)

// ---------------- device scratch --------------------------------------------
__device__ __half g_Wt[5120*1024];                // transposed weights [n][k] fp16
__device__ __half g_Xr[MROWS*DMODEL];             // fp16 X
__device__ __half g_Q [BATCH*NHEADS*LSEQ*DHEAD];  // [b,h,l,e]
__device__ __half g_K [BATCH*NHEADS*LSEQ*DHEAD];
__device__ __half g_Vt[BATCH*NHEADS*DHEAD*LSEQ];  // [b,h,v,l]
__device__ float  g_Yn[MROWS*DMODEL];
__device__ __half g_Sx[MROWS*DMODEL];             // silu(G)*Yn fp16
__device__ float g_qc[LSEQ*64];
__device__ float g_qs[LSEQ*64];
__device__ float g_kc[LSEQ*64];
__device__ float g_ks[LSEQ*64];
__device__ float g_pn[NHEADS*LSEQ];               // gamma^l
__device__ float g_pm[NHEADS*LSEQ];               // gamma^-l
__device__ int   g_win[NHEADS];                   // decay window (elements)

// ---------------- helpers ----------------------------------------------------
__device__ __forceinline__ uint32_t smem_u32(const void* p) {
    uint32_t a;
    asm("{ .reg .u64 t; cvta.to.shared.u64 t, %1; cvt.u32.u64 %0, t; }" : "=r"(a) : "l"(p));
    return a;
}
__device__ __forceinline__ void mma16(float d[4], uint32_t a0, uint32_t a1, uint32_t a2, uint32_t a3,
                                      uint32_t b0, uint32_t b1) {
    asm volatile(
        "mma.sync.aligned.m16n8k16.row.col.f32.f16.f16.f32 "
        "{%0,%1,%2,%3}, {%4,%5,%6,%7}, {%8,%9}, {%0,%1,%2,%3};"
        : "+f"(d[0]), "+f"(d[1]), "+f"(d[2]), "+f"(d[3])
        : "r"(a0), "r"(a1), "r"(a2), "r"(a3), "r"(b0), "r"(b1));
}
#define LDU(p) (*(const uint32_t*)(p))
#define CP16(dst, src)  asm volatile("cp.async.cg.shared.global [%0], [%1], 16;" :: "r"(dst), "l"(src) : "memory")
#define CPCOMMIT()      asm volatile("cp.async.commit_group;" ::: "memory")
#define CPWAIT0()       asm volatile("cp.async.wait_group 0;" ::: "memory")
#define CPWAIT1()       asm volatile("cp.async.wait_group 1;" ::: "memory")

// ---------------- table init -------------------------------------------------
__global__ void init_tables_kernel() {
    int idx = blockIdx.x*blockDim.x + threadIdx.x;
    if (idx < LSEQ*64) {
        int l = idx >> 6, j = idx & 63;
        float dh = (float)DHEAD;
        float base = (2.f*(float)j + 0.4f*dh) / (1.4f*dh);
        float scale = powf(base, (float)l / 512.0f);
        float inv_freq = powf(10000.0f, -(float)j / 64.0f);
        float arg = (float)l * inv_freq;
        float sv = sinf(arg), cv = cosf(arg);
        g_qc[idx] = cv * scale;
        g_qs[idx] = sv * scale;
        float iscale = 1.0f / scale;
        g_kc[idx] = cv * iscale;
        g_ks[idx] = sv * iscale;
    }
    if (idx < NHEADS*LSEQ) {
        int h = idx >> 11, k = idx & (LSEQ-1);
        float lg0 = logf(1.0f/32.0f), lg1 = logf(1.0f/512.0f);
        float lg = lg0 + (lg1 - lg0) * ((float)h / (float)(NHEADS-1));
        float gamma = 1.0f - expf(lg);
        double lng = (double)logf(gamma);
        g_pn[idx] = (float)exp((double)k * lng);
        g_pm[idx] = (float)exp(-(double)k * lng);
        if (k == 0) {
            double W = 11.512925 / (-lng);
            g_win[h] = (W >= 2047.0) ? 2047 : (int)W;
        }
    }
}

// ---------------- X -> fp16 --------------------------------------------------
__global__ void roundx_kernel(const float* __restrict__ X) {
    int idx = blockIdx.x*blockDim.x + threadIdx.x;   // over /8
    float4 v0 = ((const float4*)X)[idx*2];
    float4 v1 = ((const float4*)X)[idx*2 + 1];
    __half2 h[4];
    h[0] = __floats2half2_rn(v0.x, v0.y);
    h[1] = __floats2half2_rn(v0.z, v0.w);
    h[2] = __floats2half2_rn(v1.x, v1.y);
    h[3] = __floats2half2_rn(v1.z, v1.w);
    *(uint4*)(g_Xr + (size_t)idx*8) = *(uint4*)h;
}

// ---------------- weight transpose -> fp16 ----------------------------------
__global__ void wtrans_kernel(const float* __restrict__ WQ, const float* __restrict__ WK,
                              const float* __restrict__ WV, const float* __restrict__ WG,
                              const float* __restrict__ WO) {
    __shared__ float t[32][33];
    int kT = blockIdx.x << 5, nT = blockIdx.y << 5;
    int tx = threadIdx.x, ty = threadIdx.y;   // 32 x 8
    #pragma unroll
    for (int r = 0; r < 4; r++) {
        int n = nT + tx, k = kT + ty + 8*r;
        float v;
        if (n < 3072) {
            int sel = n >> 10, h = (n >> 7) & 7, e = n & 127;
            const float* W = (sel == 0) ? WQ : (sel == 1) ? WK : WV;
            v = W[(size_t)h*131072 + (size_t)k*128 + e];
        } else if (n < 4096) {
            v = WG[(size_t)k*1024 + (n - 3072)];
        } else {
            v = WO[(size_t)k*1024 + (n - 4096)];
        }
        t[ty + 8*r][tx] = v;
    }
    __syncthreads();
    #pragma unroll
    for (int r = 0; r < 4; r++) {
        int n = nT + ty + 8*r, k = kT + tx;
        g_Wt[(size_t)n*1024 + k] = __float2half(t[tx][ty + 8*r]);
    }
}

// ---------------- unified fp16 mma GEMM: 3-stage, ks-pipelined ---------------
#define MM_SMEM (110592)
__global__ __launch_bounds__(256, 2) void mm_kernel(float* __restrict__ Cout, int mode, int wRowOff) {
    extern __shared__ __half smh[];
    const int tid = threadIdx.x;
    const int wid = tid >> 5, lane = tid & 31;
    const int q = lane >> 2, tq = lane & 3;
    const int wm = wid & 3, wn = wid >> 2;
    const int rb = blockIdx.y << 7, cb = blockIdx.x << 7;

    const __half* Ap = ((mode == 2) ? g_Sx : g_Xr) + (size_t)rb * 1024;
    const __half* Bp = g_Wt + (size_t)(wRowOff + cb) * 1024;

    uint32_t smb = smem_u32(smh);
    auto issue_chunk = [&](int kc, int s) {
        int kt = kc * 64;
        uint32_t ab = smb + (uint32_t)s * 18432u;
        uint32_t bb = smb + 55296u + (uint32_t)s * 18432u;
        #pragma unroll
        for (int i = 0; i < 4; i++) {
            int ch = tid + (i << 8);
            int r = ch >> 3, c8 = (ch & 7) << 3;
            CP16(ab + (uint32_t)(r*72 + c8)*2u, Ap + (size_t)r*1024 + kt + c8);
            CP16(bb + (uint32_t)(r*72 + c8)*2u, Bp + (size_t)r*1024 + kt + c8);
        }
        CPCOMMIT();
    };

    float acc[2][8][4];
    #pragma unroll
    for (int mi = 0; mi < 2; mi++)
        #pragma unroll
        for (int ni = 0; ni < 8; ni++)
            #pragma unroll
            for (int c = 0; c < 4; c++) acc[mi][ni][c] = 0.0f;

    issue_chunk(0, 0);
    issue_chunk(1, 1);

    const int ar0 = wm*32 + q;          // A fragment row base
    const int bn0 = wn*64 + q;          // B fragment col base

    #pragma unroll 1
    for (int k = 0; k < 16; k++) {
        int s = k % 3;
        if (k + 2 < 16) CPWAIT1(); else CPWAIT0();
        __syncthreads();
        if (k + 2 < 16) issue_chunk(k + 2, (k + 2) % 3);

        const __half* A_ = smh + s * 9216;
        const __half* B_ = smh + 27648 + s * 9216;

        uint32_t af[2][2][4];
        uint32_t bf[2][8][2];
        // preload ks = 0 into slot 0
        {
            int c = 2*tq;
            #pragma unroll
            for (int mi = 0; mi < 2; mi++) {
                int r = ar0 + mi*16;
                af[0][mi][0] = LDU(A_ + r*72 + c);
                af[0][mi][1] = LDU(A_ + (r+8)*72 + c);
                af[0][mi][2] = LDU(A_ + r*72 + c + 8);
                af[0][mi][3] = LDU(A_ + (r+8)*72 + c + 8);
            }
            #pragma unroll
            for (int ni = 0; ni < 8; ni++) {
                int n = bn0 + ni*8;
                bf[0][ni][0] = LDU(B_ + n*72 + c);
                bf[0][ni][1] = LDU(B_ + n*72 + c + 8);
            }
        }
        #pragma unroll
        for (int ks = 0; ks < 4; ks++) {
            int cur = ks & 1;
            if (ks < 3) {
                int nxt = cur ^ 1;
                int c = (ks+1)*16 + 2*tq;
                #pragma unroll
                for (int mi = 0; mi < 2; mi++) {
                    int r = ar0 + mi*16;
                    af[nxt][mi][0] = LDU(A_ + r*72 + c);
                    af[nxt][mi][1] = LDU(A_ + (r+8)*72 + c);
                    af[nxt][mi][2] = LDU(A_ + r*72 + c + 8);
                    af[nxt][mi][3] = LDU(A_ + (r+8)*72 + c + 8);
                }
                #pragma unroll
                for (int ni = 0; ni < 8; ni++) {
                    int n = bn0 + ni*8;
                    bf[nxt][ni][0] = LDU(B_ + n*72 + c);
                    bf[nxt][ni][1] = LDU(B_ + n*72 + c + 8);
                }
            }
            #pragma unroll
            for (int ni = 0; ni < 8; ni++) {
                mma16(acc[0][ni], af[cur][0][0], af[cur][0][1], af[cur][0][2], af[cur][0][3],
                      bf[cur][ni][0], bf[cur][ni][1]);
                mma16(acc[1][ni], af[cur][1][0], af[cur][1][1], af[cur][1][2], af[cur][1][3],
                      bf[cur][ni][0], bf[cur][ni][1]);
            }
        }
    }

    // ---------------- epilogue ----------------
    int sel = 0, hh = 0;
    if (mode == 0) { sel = blockIdx.x >> 3; hh = blockIdx.x & 7; }

    #pragma unroll
    for (int mi = 0; mi < 2; mi++) {
        #pragma unroll
        for (int half_ = 0; half_ < 2; half_++) {
            int row = rb + wm*32 + mi*16 + q + half_*8;
            int bb = row >> 11, l = row & (LSEQ - 1);
            #pragma unroll
            for (int ni = 0; ni < 8; ni++) {
                int colb = wn*64 + ni*8 + 2*tq;
                float x1 = acc[mi][ni][half_*2 + 0];
                float x2 = acc[mi][ni][half_*2 + 1];
                if (mode == 0) {
                    size_t hbase = (size_t)(bb*NHEADS + hh);
                    if (sel == 2) {
                        __half* vt = g_Vt + hbase * (size_t)(DHEAD*LSEQ);
                        vt[(size_t)colb * LSEQ + l]       = __float2half(x1);
                        vt[(size_t)(colb + 1) * LSEQ + l] = __float2half(x2);
                    } else {
                        const float* ct = (sel == 0) ? g_qc : g_kc;
                        const float* st = (sel == 0) ? g_qs : g_ks;
                        int jj = colb >> 1;
                        float cv = ct[l*64 + jj], sv = st[l*64 + jj];
                        __half2 o = __floats2half2_rn(x1*cv - x2*sv, x2*cv + x1*sv);
                        __half* dst = ((sel == 0) ? g_Q : g_K) + (hbase*LSEQ + l)*DHEAD + colb;
                        *(__half2*)dst = o;
                    }
                } else if (mode == 1) {
                    size_t off = (size_t)row*1024 + cb + colb;
                    float2 yn = *(const float2*)(g_Yn + off);
                    __half2 o = __floats2half2_rn((x1 / (1.0f + expf(-x1))) * yn.x,
                                                  (x2 / (1.0f + expf(-x2))) * yn.y);
                    *(__half2*)(g_Sx + off) = o;
                } else {
                    size_t off = (size_t)row*1024 + cb + colb;
                    *(float2*)(Cout + off) = make_float2(x1, x2);
                }
            }
        }
    }
}

// ---------------- attention + fused groupnorm (R12 known-good) ---------------
#define QS_O  0
#define KS0_O 17408
#define KS1_O 26112
#define VS_O  34816
#define SS_O  44032
#define ATT_SMEM (53248*2)
__global__ __launch_bounds__(256, 2) void attn_kernel(
    const float* __restrict__ gw, const float* __restrict__ gb)
{
    extern __shared__ __half smh[];
    __half* Qs = smh + QS_O;
    __half* Ks[2] = { smh + KS0_O, smh + KS1_O };
    __half* Vs = smh + VS_O;
    __half* Ss = smh + SS_O;
    uint32_t smb = smem_u32(smh);
    uint32_t qsb = smb + QS_O*2u;
    uint32_t ksb[2] = { smb + KS0_O*2u, smb + KS1_O*2u };
    uint32_t vsb = smb + VS_O*2u;

    const int tid = threadIdx.x;
    const int wid = tid >> 5, lane = tid & 31;
    const int q = lane >> 2, tq = lane & 3;
    const int wm = wid & 3, wn = wid >> 2;

    int nt = (int)(gridDim.x - 1) - (int)blockIdx.x;   // big tiles first
    int h = blockIdx.y, b = blockIdx.z;
    int nb = nt << 7;

    size_t hb = (size_t)(b*NHEADS + h);
    const __half* Qg = g_Q + hb * (size_t)(LSEQ*DHEAD);
    const __half* Kg = g_K + hb * (size_t)(LSEQ*DHEAD);
    const __half* Vg = g_Vt + hb * (size_t)(DHEAD*LSEQ);
    const float* pm = g_pm + h*LSEQ;

    int nMt = 2*nt + 2;
    int mt0 = (nb - g_win[h]) >> 6;
    if (mt0 < 0) mt0 = 0;

    float pn[2][2];
    #pragma unroll
    for (int mi = 0; mi < 2; mi++)
        #pragma unroll
        for (int hf = 0; hf < 2; hf++)
            pn[mi][hf] = g_pn[h*LSEQ + nb + wm*32 + mi*16 + q + hf*8];

    // prologue: Q + K[mt0], one commit group
    {
        int r = tid >> 1, part = (tid & 1) * 64;
        const __half* src = Qg + (size_t)(nb + r)*DHEAD + part;
        #pragma unroll
        for (int i = 0; i < 8; i++)
            CP16(qsb + (uint32_t)(r*136 + part + i*8)*2u, src + i*8);
        int kr = tid >> 2, kc = (tid & 3) * 32;
        const __half* ksrc = Kg + (size_t)(mt0*64 + kr)*DHEAD + kc;
        #pragma unroll
        for (int i = 0; i < 4; i++)
            CP16(ksb[0] + (uint32_t)(kr*136 + kc + i*8)*2u, ksrc + i*8);
        CPCOMMIT();
    }

    float yacc[2][8][4];
    #pragma unroll
    for (int mi = 0; mi < 2; mi++)
        #pragma unroll
        for (int ni = 0; ni < 8; ni++)
            #pragma unroll
            for (int c = 0; c < 4; c++) yacc[mi][ni][c] = 0.0f;

    #pragma unroll 1
    for (int mt = mt0; mt < nMt; mt++) {
        int mb_ = mt << 6;
        int buf = (mt - mt0) & 1;
        CPWAIT0();
        __syncthreads();

        {
            int vr = tid >> 1, vc = (tid & 1) * 32;
            const __half* vsrc = Vg + (size_t)vr*LSEQ + mb_ + vc;
            #pragma unroll
            for (int i = 0; i < 4; i++)
                CP16(vsb + (uint32_t)(vr*72 + vc + i*8)*2u, vsrc + i*8);
            CPCOMMIT();
        }
        if (mt + 1 < nMt) {
            int kr = tid >> 2, kc = (tid & 3) * 32;
            const __half* ksrc = Kg + (size_t)(mb_ + 64 + kr)*DHEAD + kc;
            #pragma unroll
            for (int i = 0; i < 4; i++)
                CP16(ksb[buf^1] + (uint32_t)(kr*136 + kc + i*8)*2u, ksrc + i*8);
            CPCOMMIT();
        }

        const __half* K_ = Ks[buf];
        float sacc[2][4][4];
        #pragma unroll
        for (int mi = 0; mi < 2; mi++)
            #pragma unroll
            for (int ni = 0; ni < 4; ni++)
                #pragma unroll
                for (int c = 0; c < 4; c++) sacc[mi][ni][c] = 0.0f;
        #pragma unroll
        for (int ks = 0; ks < 8; ks++) {
            int c = ks*16 + 2*tq;
            uint32_t af[2][4];
            uint32_t bf[4][2];
            #pragma unroll
            for (int mi = 0; mi < 2; mi++) {
                int r = wm*32 + mi*16 + q;
                af[mi][0] = LDU(Qs + r*136 + c);
                af[mi][1] = LDU(Qs + (r+8)*136 + c);
                af[mi][2] = LDU(Qs + r*136 + c + 8);
                af[mi][3] = LDU(Qs + (r+8)*136 + c + 8);
            }
            #pragma unroll
            for (int ni = 0; ni < 4; ni++) {
                int m = wn*32 + ni*8 + q;
                bf[ni][0] = LDU(K_ + m*136 + c);
                bf[ni][1] = LDU(K_ + m*136 + c + 8);
            }
            #pragma unroll
            for (int ni = 0; ni < 4; ni++) {
                mma16(sacc[0][ni], af[0][0], af[0][1], af[0][2], af[0][3], bf[ni][0], bf[ni][1]);
                mma16(sacc[1][ni], af[1][0], af[1][1], af[1][2], af[1][3], bf[ni][0], bf[ni][1]);
            }
        }

        #pragma unroll
        for (int mi = 0; mi < 2; mi++) {
            #pragma unroll
            for (int hf = 0; hf < 2; hf++) {
                int r = wm*32 + mi*16 + q + hf*8;
                int n_ = nb + r;
                float pnv = pn[mi][hf];
                #pragma unroll
                for (int ni = 0; ni < 4; ni++) {
                    int m = wn*32 + ni*8 + 2*tq;
                    int mg = mb_ + m;
                    float2 ip = *(const float2*)(pm + mg);
                    float v0 = (n_ >= mg) ? sacc[mi][ni][hf*2+0] * (pnv*ip.x) : 0.0f;
                    float v1 = (n_ >  mg) ? sacc[mi][ni][hf*2+1] * (pnv*ip.y) : 0.0f;
                    *(__half2*)(Ss + r*72 + m) = __floats2half2_rn(v0, v1);
                }
            }
        }
        if (mt + 1 < nMt) CPWAIT1(); else CPWAIT0();
        __syncthreads();

        #pragma unroll
        for (int ks = 0; ks < 4; ks++) {
            int c = ks*16 + 2*tq;
            uint32_t af[2][4];
            uint32_t bf[8][2];
            #pragma unroll
            for (int mi = 0; mi < 2; mi++) {
                int r = wm*32 + mi*16 + q;
                af[mi][0] = LDU(Ss + r*72 + c);
                af[mi][1] = LDU(Ss + (r+8)*72 + c);
                af[mi][2] = LDU(Ss + r*72 + c + 8);
                af[mi][3] = LDU(Ss + (r+8)*72 + c + 8);
            }
            #pragma unroll
            for (int ni = 0; ni < 8; ni++) {
                int v = wn*64 + ni*8 + q;
                bf[ni][0] = LDU(Vs + v*72 + c);
                bf[ni][1] = LDU(Vs + v*72 + c + 8);
            }
            #pragma unroll
            for (int ni = 0; ni < 8; ni++) {
                mma16(yacc[0][ni], af[0][0], af[0][1], af[0][2], af[0][3], bf[ni][0], bf[ni][1]);
                mma16(yacc[1][ni], af[1][0], af[1][1], af[1][2], af[1][3], bf[ni][0], bf[ni][1]);
            }
        }
    }

    // -------- fused group norm + transposed write to g_Yn --------------------
    __syncthreads();
    float* fb = (float*)smh;
    #pragma unroll
    for (int mi = 0; mi < 2; mi++) {
        #pragma unroll
        for (int hf = 0; hf < 2; hf++) {
            int row = wm*32 + mi*16 + hf*8 + q;
            float s = 0.0f, ss = 0.0f;
            #pragma unroll
            for (int ni = 0; ni < 8; ni++) {
                float a = yacc[mi][ni][hf*2+0], b2 = yacc[mi][ni][hf*2+1];
                s += a + b2; ss += a*a + b2*b2;
            }
            s  += __shfl_xor_sync(0xffffffffu, s, 1);
            ss += __shfl_xor_sync(0xffffffffu, ss, 1);
            s  += __shfl_xor_sync(0xffffffffu, s, 2);
            ss += __shfl_xor_sync(0xffffffffu, ss, 2);
            if (tq == 0) { fb[row*4 + wn*2] = s; fb[row*4 + wn*2 + 1] = ss; }
        }
    }
    __syncthreads();
    #pragma unroll
    for (int mi = 0; mi < 2; mi++) {
        #pragma unroll
        for (int hf = 0; hf < 2; hf++) {
            int row = wm*32 + mi*16 + hf*8 + q;
            float s  = fb[row*4 + 0] + fb[row*4 + 2];
            float ss = fb[row*4 + 1] + fb[row*4 + 3];
            float mean = s * (1.0f/DHEAD);
            float var  = ss * (1.0f/DHEAD) - mean*mean;
            float rstd = rsqrtf(var + 1e-5f);
            int l = nb + row;
            float* dst = g_Yn + ((size_t)(b*LSEQ + l))*DMODEL + h*DHEAD;
            #pragma unroll
            for (int ni = 0; ni < 8; ni++) {
                int col = wn*64 + ni*8 + 2*tq;
                float2 w2 = *(const float2*)(gw + h*DHEAD + col);
                float2 b2 = *(const float2*)(gb + h*DHEAD + col);
                float y0 = yacc[mi][ni][hf*2+0], y1 = yacc[mi][ni][hf*2+1];
                float2 o;
                o.x = (y0 - mean)*rstd*w2.x + b2.x;
                o.y = (y1 - mean)*rstd*w2.y + b2.y;
                *(float2*)(dst + col) = o;
            }
        }
    }
}

// ---------------- launch ----------------------------------------------------
extern "C" void kernel_launch(void* const* d_in, const int* in_sizes, int n_in,
                              void* d_out, int out_size) {
    const float* X  = (const float*)d_in[0];
    const float* WQ = (const float*)d_in[1];
    const float* WK = (const float*)d_in[2];
    const float* WV = (const float*)d_in[3];
    const float* WG = (const float*)d_in[4];
    const float* WO = (const float*)d_in[5];
    const float* gw = (const float*)d_in[6];
    const float* gb = (const float*)d_in[7];
    float* out = (float*)d_out;

    cudaFuncSetAttribute(mm_kernel, cudaFuncAttributeMaxDynamicSharedMemorySize, MM_SMEM);
    cudaFuncSetAttribute(attn_kernel, cudaFuncAttributeMaxDynamicSharedMemorySize, ATT_SMEM);

    init_tables_kernel<<<512, 256>>>();
    roundx_kernel<<<(MROWS*DMODEL/8)/256, 256>>>(X);
    wtrans_kernel<<<dim3(32, 160), dim3(32, 8)>>>(WQ, WK, WV, WG, WO);

    // QKV projection + rotary + V transpose
    mm_kernel<<<dim3(24, 64), 256, MM_SMEM>>>(nullptr, 0, 0);

    // retention attention + fused group norm (2 CTA/SM, decay-windowed)
    attn_kernel<<<dim3(16, NHEADS, BATCH), 256, ATT_SMEM>>>(gw, gb);

    // gate GEMM + silu*Yn
    mm_kernel<<<dim3(8, 64), 256, MM_SMEM>>>(nullptr, 1, 3072);

    // output GEMM
    mm_kernel<<<dim3(8, 64), 256, MM_SMEM>>>(out, 2, 4096);
}

// round 15
// speedup vs baseline: 1.0064x; 1.0064x over previous
#include <cuda_runtime.h>
#include <cuda_fp16.h>
#include <math.h>
#include <stdint.h>

#define BATCH 4
#define LSEQ 2048
#define DMODEL 1024
#define NHEADS 8
#define DHEAD 128
#define MROWS (BATCH*LSEQ)

// ---------------- device scratch --------------------------------------------
__device__ __half g_Wt[5120*1024];                // transposed weights [n][k] fp16
__device__ __half g_Xr[MROWS*DMODEL];             // fp16 X
__device__ __half g_Q [BATCH*NHEADS*LSEQ*DHEAD];  // [b,h,l,e]
__device__ __half g_K [BATCH*NHEADS*LSEQ*DHEAD];
__device__ __half g_Vt[BATCH*NHEADS*DHEAD*LSEQ];  // [b,h,v,l]
__device__ float  g_Yn[MROWS*DMODEL];
__device__ __half g_Sx[MROWS*DMODEL];             // silu(G)*Yn fp16
__device__ float g_qc[LSEQ*64];
__device__ float g_qs[LSEQ*64];
__device__ float g_kc[LSEQ*64];
__device__ float g_ks[LSEQ*64];
__device__ float g_pn[NHEADS*LSEQ];               // gamma^l
__device__ float g_pm[NHEADS*LSEQ];               // gamma^-l
__device__ int   g_win[NHEADS];                   // decay window (elements)

// ---------------- helpers ----------------------------------------------------
__device__ __forceinline__ uint32_t smem_u32(const void* p) {
    uint32_t a;
    asm("{ .reg .u64 t; cvta.to.shared.u64 t, %1; cvt.u32.u64 %0, t; }" : "=r"(a) : "l"(p));
    return a;
}
__device__ __forceinline__ void mma16(float d[4], uint32_t a0, uint32_t a1, uint32_t a2, uint32_t a3,
                                      uint32_t b0, uint32_t b1) {
    asm volatile(
        "mma.sync.aligned.m16n8k16.row.col.f32.f16.f16.f32 "
        "{%0,%1,%2,%3}, {%4,%5,%6,%7}, {%8,%9}, {%0,%1,%2,%3};"
        : "+f"(d[0]), "+f"(d[1]), "+f"(d[2]), "+f"(d[3])
        : "r"(a0), "r"(a1), "r"(a2), "r"(a3), "r"(b0), "r"(b1));
}
#define LDU(p) (*(const uint32_t*)(p))
#define CP16(dst, src)  asm volatile("cp.async.cg.shared.global [%0], [%1], 16;" :: "r"(dst), "l"(src) : "memory")
#define CPCOMMIT()      asm volatile("cp.async.commit_group;" ::: "memory")
#define CPWAIT0()       asm volatile("cp.async.wait_group 0;" ::: "memory")
#define CPWAIT1()       asm volatile("cp.async.wait_group 1;" ::: "memory")

// ---------------- merged prep: tables + X->fp16 ------------------------------
__global__ void prep_kernel(const float* __restrict__ X) {
    int idx = blockIdx.x*blockDim.x + threadIdx.x;   // 1,048,576 threads
    // X rounding: 8 floats per thread
    {
        float4 v0 = ((const float4*)X)[idx*2];
        float4 v1 = ((const float4*)X)[idx*2 + 1];
        __half2 h[4];
        h[0] = __floats2half2_rn(v0.x, v0.y);
        h[1] = __floats2half2_rn(v0.z, v0.w);
        h[2] = __floats2half2_rn(v1.x, v1.y);
        h[3] = __floats2half2_rn(v1.z, v1.w);
        *(uint4*)(g_Xr + (size_t)idx*8) = *(uint4*)h;
    }
    if (idx < LSEQ*64) {
        int l = idx >> 6, j = idx & 63;
        float dh = (float)DHEAD;
        float base = (2.f*(float)j + 0.4f*dh) / (1.4f*dh);
        float scale = powf(base, (float)l / 512.0f);
        float inv_freq = powf(10000.0f, -(float)j / 64.0f);
        float arg = (float)l * inv_freq;
        float sv = sinf(arg), cv = cosf(arg);
        g_qc[idx] = cv * scale;
        g_qs[idx] = sv * scale;
        float iscale = 1.0f / scale;
        g_kc[idx] = cv * iscale;
        g_ks[idx] = sv * iscale;
    }
    if (idx < NHEADS*LSEQ) {
        int h = idx >> 11, k = idx & (LSEQ-1);
        float lg0 = logf(1.0f/32.0f), lg1 = logf(1.0f/512.0f);
        float lg = lg0 + (lg1 - lg0) * ((float)h / (float)(NHEADS-1));
        float gamma = 1.0f - expf(lg);
        double lng = (double)logf(gamma);
        g_pn[idx] = (float)exp((double)k * lng);
        g_pm[idx] = (float)exp(-(double)k * lng);
        if (k == 0) {
            double W = 11.512925 / (-lng);
            g_win[h] = (W >= 2047.0) ? 2047 : (int)W;
        }
    }
}

// ---------------- weight transpose -> fp16 ----------------------------------
__global__ void wtrans_kernel(const float* __restrict__ WQ, const float* __restrict__ WK,
                              const float* __restrict__ WV, const float* __restrict__ WG,
                              const float* __restrict__ WO) {
    __shared__ float t[32][33];
    int kT = blockIdx.x << 5, nT = blockIdx.y << 5;
    int tx = threadIdx.x, ty = threadIdx.y;   // 32 x 8
    #pragma unroll
    for (int r = 0; r < 4; r++) {
        int n = nT + tx, k = kT + ty + 8*r;
        float v;
        if (n < 3072) {
            int sel = n >> 10, h = (n >> 7) & 7, e = n & 127;
            const float* W = (sel == 0) ? WQ : (sel == 1) ? WK : WV;
            v = W[(size_t)h*131072 + (size_t)k*128 + e];
        } else if (n < 4096) {
            v = WG[(size_t)k*1024 + (n - 3072)];
        } else {
            v = WO[(size_t)k*1024 + (n - 4096)];
        }
        t[ty + 8*r][tx] = v;
    }
    __syncthreads();
    #pragma unroll
    for (int r = 0; r < 4; r++) {
        int n = nT + ty + 8*r, k = kT + tx;
        g_Wt[(size_t)n*1024 + k] = __float2half(t[tx][ty + 8*r]);
    }
}

// ---------------- unified fp16 mma GEMM: 3-stage, 1 barrier/chunk ------------
#define MM_SMEM (110592)
__global__ __launch_bounds__(256) void mm_kernel(float* __restrict__ Cout, int mode, int wRowOff) {
    extern __shared__ __half smh[];
    const int tid = threadIdx.x;
    const int wid = tid >> 5, lane = tid & 31;
    const int q = lane >> 2, tq = lane & 3;
    const int wm = wid & 3, wn = wid >> 2;
    const int rb = blockIdx.y << 7, cb = blockIdx.x << 7;

    const __half* Ap = ((mode == 2) ? g_Sx : g_Xr) + (size_t)rb * 1024;
    const __half* Bp = g_Wt + (size_t)(wRowOff + cb) * 1024;

    uint32_t smb = smem_u32(smh);
    auto issue_chunk = [&](int kc, int s) {
        int kt = kc * 64;
        uint32_t ab = smb + (uint32_t)s * 18432u;
        uint32_t bb = smb + 55296u + (uint32_t)s * 18432u;
        #pragma unroll
        for (int i = 0; i < 4; i++) {
            int ch = tid + (i << 8);
            int r = ch >> 3, c8 = (ch & 7) << 3;
            CP16(ab + (uint32_t)(r*72 + c8)*2u, Ap + (size_t)r*1024 + kt + c8);
            CP16(bb + (uint32_t)(r*72 + c8)*2u, Bp + (size_t)r*1024 + kt + c8);
        }
        CPCOMMIT();
    };

    float acc[2][8][4];
    #pragma unroll
    for (int mi = 0; mi < 2; mi++)
        #pragma unroll
        for (int ni = 0; ni < 8; ni++)
            #pragma unroll
            for (int c = 0; c < 4; c++) acc[mi][ni][c] = 0.0f;

    issue_chunk(0, 0);
    issue_chunk(1, 1);

    #pragma unroll 1
    for (int k = 0; k < 16; k++) {
        int s = k % 3;
        if (k + 2 < 16) CPWAIT1(); else CPWAIT0();
        __syncthreads();
        if (k + 2 < 16) issue_chunk(k + 2, (k + 2) % 3);

        const __half* A_ = smh + s * 9216;
        const __half* B_ = smh + 27648 + s * 9216;
        #pragma unroll
        for (int ks = 0; ks < 4; ks++) {
            int c = ks*16 + 2*tq;
            uint32_t af[2][4];
            uint32_t bf[8][2];
            #pragma unroll
            for (int mi = 0; mi < 2; mi++) {
                int r = wm*32 + mi*16 + q;
                af[mi][0] = LDU(A_ + r*72 + c);
                af[mi][1] = LDU(A_ + (r+8)*72 + c);
                af[mi][2] = LDU(A_ + r*72 + c + 8);
                af[mi][3] = LDU(A_ + (r+8)*72 + c + 8);
            }
            #pragma unroll
            for (int ni = 0; ni < 8; ni++) {
                int n = wn*64 + ni*8 + q;
                bf[ni][0] = LDU(B_ + n*72 + c);
                bf[ni][1] = LDU(B_ + n*72 + c + 8);
            }
            #pragma unroll
            for (int ni = 0; ni < 8; ni++) {
                mma16(acc[0][ni], af[0][0], af[0][1], af[0][2], af[0][3], bf[ni][0], bf[ni][1]);
                mma16(acc[1][ni], af[1][0], af[1][1], af[1][2], af[1][3], bf[ni][0], bf[ni][1]);
            }
        }
    }

    // ---------------- epilogue ----------------
    int sel = 0, hh = 0;
    if (mode == 0) { sel = blockIdx.x >> 3; hh = blockIdx.x & 7; }

    #pragma unroll
    for (int mi = 0; mi < 2; mi++) {
        #pragma unroll
        for (int half_ = 0; half_ < 2; half_++) {
            int row = rb + wm*32 + mi*16 + q + half_*8;
            int bb = row >> 11, l = row & (LSEQ - 1);
            #pragma unroll
            for (int ni = 0; ni < 8; ni++) {
                int colb = wn*64 + ni*8 + 2*tq;
                float x1 = acc[mi][ni][half_*2 + 0];
                float x2 = acc[mi][ni][half_*2 + 1];
                if (mode == 0) {
                    size_t hbase = (size_t)(bb*NHEADS + hh);
                    if (sel == 2) {
                        __half* vt = g_Vt + hbase * (size_t)(DHEAD*LSEQ);
                        vt[(size_t)colb * LSEQ + l]       = __float2half(x1);
                        vt[(size_t)(colb + 1) * LSEQ + l] = __float2half(x2);
                    } else {
                        const float* ct = (sel == 0) ? g_qc : g_kc;
                        const float* st = (sel == 0) ? g_qs : g_ks;
                        int jj = colb >> 1;
                        float cv = ct[l*64 + jj], sv = st[l*64 + jj];
                        __half2 o = __floats2half2_rn(x1*cv - x2*sv, x2*cv + x1*sv);
                        __half* dst = ((sel == 0) ? g_Q : g_K) + (hbase*LSEQ + l)*DHEAD + colb;
                        *(__half2*)dst = o;
                    }
                } else if (mode == 1) {
                    size_t off = (size_t)row*1024 + cb + colb;
                    float2 yn = *(const float2*)(g_Yn + off);
                    __half2 o = __floats2half2_rn((x1 / (1.0f + expf(-x1))) * yn.x,
                                                  (x2 / (1.0f + expf(-x2))) * yn.y);
                    *(__half2*)(g_Sx + off) = o;
                } else {
                    size_t off = (size_t)row*1024 + cb + colb;
                    *(float2*)(Cout + off) = make_float2(x1, x2);
                }
            }
        }
    }
}

// ---------------- attention + fused groupnorm (R12 known-good) ---------------
#define QS_O  0
#define KS0_O 17408
#define KS1_O 26112
#define VS_O  34816
#define SS_O  44032
#define ATT_SMEM (53248*2)
__global__ __launch_bounds__(256, 2) void attn_kernel(
    const float* __restrict__ gw, const float* __restrict__ gb)
{
    extern __shared__ __half smh[];
    __half* Qs = smh + QS_O;
    __half* Ks[2] = { smh + KS0_O, smh + KS1_O };
    __half* Vs = smh + VS_O;
    __half* Ss = smh + SS_O;
    uint32_t smb = smem_u32(smh);
    uint32_t qsb = smb + QS_O*2u;
    uint32_t ksb[2] = { smb + KS0_O*2u, smb + KS1_O*2u };
    uint32_t vsb = smb + VS_O*2u;

    const int tid = threadIdx.x;
    const int wid = tid >> 5, lane = tid & 31;
    const int q = lane >> 2, tq = lane & 3;
    const int wm = wid & 3, wn = wid >> 2;

    int nt = (int)(gridDim.x - 1) - (int)blockIdx.x;   // big tiles first
    int h = blockIdx.y, b = blockIdx.z;
    int nb = nt << 7;

    size_t hb = (size_t)(b*NHEADS + h);
    const __half* Qg = g_Q + hb * (size_t)(LSEQ*DHEAD);
    const __half* Kg = g_K + hb * (size_t)(LSEQ*DHEAD);
    const __half* Vg = g_Vt + hb * (size_t)(DHEAD*LSEQ);
    const float* pm = g_pm + h*LSEQ;

    int nMt = 2*nt + 2;
    int mt0 = (nb - g_win[h]) >> 6;
    if (mt0 < 0) mt0 = 0;

    float pn[2][2];
    #pragma unroll
    for (int mi = 0; mi < 2; mi++)
        #pragma unroll
        for (int hf = 0; hf < 2; hf++)
            pn[mi][hf] = g_pn[h*LSEQ + nb + wm*32 + mi*16 + q + hf*8];

    // prologue: Q + K[mt0], one commit group
    {
        int r = tid >> 1, part = (tid & 1) * 64;
        const __half* src = Qg + (size_t)(nb + r)*DHEAD + part;
        #pragma unroll
        for (int i = 0; i < 8; i++)
            CP16(qsb + (uint32_t)(r*136 + part + i*8)*2u, src + i*8);
        int kr = tid >> 2, kc = (tid & 3) * 32;
        const __half* ksrc = Kg + (size_t)(mt0*64 + kr)*DHEAD + kc;
        #pragma unroll
        for (int i = 0; i < 4; i++)
            CP16(ksb[0] + (uint32_t)(kr*136 + kc + i*8)*2u, ksrc + i*8);
        CPCOMMIT();
    }

    float yacc[2][8][4];
    #pragma unroll
    for (int mi = 0; mi < 2; mi++)
        #pragma unroll
        for (int ni = 0; ni < 8; ni++)
            #pragma unroll
            for (int c = 0; c < 4; c++) yacc[mi][ni][c] = 0.0f;

    #pragma unroll 1
    for (int mt = mt0; mt < nMt; mt++) {
        int mb_ = mt << 6;
        int buf = (mt - mt0) & 1;
        CPWAIT0();
        __syncthreads();

        {
            int vr = tid >> 1, vc = (tid & 1) * 32;
            const __half* vsrc = Vg + (size_t)vr*LSEQ + mb_ + vc;
            #pragma unroll
            for (int i = 0; i < 4; i++)
                CP16(vsb + (uint32_t)(vr*72 + vc + i*8)*2u, vsrc + i*8);
            CPCOMMIT();
        }
        if (mt + 1 < nMt) {
            int kr = tid >> 2, kc = (tid & 3) * 32;
            const __half* ksrc = Kg + (size_t)(mb_ + 64 + kr)*DHEAD + kc;
            #pragma unroll
            for (int i = 0; i < 4; i++)
                CP16(ksb[buf^1] + (uint32_t)(kr*136 + kc + i*8)*2u, ksrc + i*8);
            CPCOMMIT();
        }

        const __half* K_ = Ks[buf];
        float sacc[2][4][4];
        #pragma unroll
        for (int mi = 0; mi < 2; mi++)
            #pragma unroll
            for (int ni = 0; ni < 4; ni++)
                #pragma unroll
                for (int c = 0; c < 4; c++) sacc[mi][ni][c] = 0.0f;
        #pragma unroll
        for (int ks = 0; ks < 8; ks++) {
            int c = ks*16 + 2*tq;
            uint32_t af[2][4];
            uint32_t bf[4][2];
            #pragma unroll
            for (int mi = 0; mi < 2; mi++) {
                int r = wm*32 + mi*16 + q;
                af[mi][0] = LDU(Qs + r*136 + c);
                af[mi][1] = LDU(Qs + (r+8)*136 + c);
                af[mi][2] = LDU(Qs + r*136 + c + 8);
                af[mi][3] = LDU(Qs + (r+8)*136 + c + 8);
            }
            #pragma unroll
            for (int ni = 0; ni < 4; ni++) {
                int m = wn*32 + ni*8 + q;
                bf[ni][0] = LDU(K_ + m*136 + c);
                bf[ni][1] = LDU(K_ + m*136 + c + 8);
            }
            #pragma unroll
            for (int ni = 0; ni < 4; ni++) {
                mma16(sacc[0][ni], af[0][0], af[0][1], af[0][2], af[0][3], bf[ni][0], bf[ni][1]);
                mma16(sacc[1][ni], af[1][0], af[1][1], af[1][2], af[1][3], bf[ni][0], bf[ni][1]);
            }
        }

        #pragma unroll
        for (int mi = 0; mi < 2; mi++) {
            #pragma unroll
            for (int hf = 0; hf < 2; hf++) {
                int r = wm*32 + mi*16 + q + hf*8;
                int n_ = nb + r;
                float pnv = pn[mi][hf];
                #pragma unroll
                for (int ni = 0; ni < 4; ni++) {
                    int m = wn*32 + ni*8 + 2*tq;
                    int mg = mb_ + m;
                    float2 ip = *(const float2*)(pm + mg);
                    float v0 = (n_ >= mg) ? sacc[mi][ni][hf*2+0] * (pnv*ip.x) : 0.0f;
                    float v1 = (n_ >  mg) ? sacc[mi][ni][hf*2+1] * (pnv*ip.y) : 0.0f;
                    *(__half2*)(Ss + r*72 + m) = __floats2half2_rn(v0, v1);
                }
            }
        }
        if (mt + 1 < nMt) CPWAIT1(); else CPWAIT0();
        __syncthreads();

        #pragma unroll
        for (int ks = 0; ks < 4; ks++) {
            int c = ks*16 + 2*tq;
            uint32_t af[2][4];
            uint32_t bf[8][2];
            #pragma unroll
            for (int mi = 0; mi < 2; mi++) {
                int r = wm*32 + mi*16 + q;
                af[mi][0] = LDU(Ss + r*72 + c);
                af[mi][1] = LDU(Ss + (r+8)*72 + c);
                af[mi][2] = LDU(Ss + r*72 + c + 8);
                af[mi][3] = LDU(Ss + (r+8)*72 + c + 8);
            }
            #pragma unroll
            for (int ni = 0; ni < 8; ni++) {
                int v = wn*64 + ni*8 + q;
                bf[ni][0] = LDU(Vs + v*72 + c);
                bf[ni][1] = LDU(Vs + v*72 + c + 8);
            }
            #pragma unroll
            for (int ni = 0; ni < 8; ni++) {
                mma16(yacc[0][ni], af[0][0], af[0][1], af[0][2], af[0][3], bf[ni][0], bf[ni][1]);
                mma16(yacc[1][ni], af[1][0], af[1][1], af[1][2], af[1][3], bf[ni][0], bf[ni][1]);
            }
        }
    }

    // -------- fused group norm + transposed write to g_Yn --------------------
    __syncthreads();
    float* fb = (float*)smh;
    #pragma unroll
    for (int mi = 0; mi < 2; mi++) {
        #pragma unroll
        for (int hf = 0; hf < 2; hf++) {
            int row = wm*32 + mi*16 + hf*8 + q;
            float s = 0.0f, ss = 0.0f;
            #pragma unroll
            for (int ni = 0; ni < 8; ni++) {
                float a = yacc[mi][ni][hf*2+0], b2 = yacc[mi][ni][hf*2+1];
                s += a + b2; ss += a*a + b2*b2;
            }
            s  += __shfl_xor_sync(0xffffffffu, s, 1);
            ss += __shfl_xor_sync(0xffffffffu, ss, 1);
            s  += __shfl_xor_sync(0xffffffffu, s, 2);
            ss += __shfl_xor_sync(0xffffffffu, ss, 2);
            if (tq == 0) { fb[row*4 + wn*2] = s; fb[row*4 + wn*2 + 1] = ss; }
        }
    }
    __syncthreads();
    #pragma unroll
    for (int mi = 0; mi < 2; mi++) {
        #pragma unroll
        for (int hf = 0; hf < 2; hf++) {
            int row = wm*32 + mi*16 + hf*8 + q;
            float s  = fb[row*4 + 0] + fb[row*4 + 2];
            float ss = fb[row*4 + 1] + fb[row*4 + 3];
            float mean = s * (1.0f/DHEAD);
            float var  = ss * (1.0f/DHEAD) - mean*mean;
            float rstd = rsqrtf(var + 1e-5f);
            int l = nb + row;
            float* dst = g_Yn + ((size_t)(b*LSEQ + l))*DMODEL + h*DHEAD;
            #pragma unroll
            for (int ni = 0; ni < 8; ni++) {
                int col = wn*64 + ni*8 + 2*tq;
                float2 w2 = *(const float2*)(gw + h*DHEAD + col);
                float2 b2 = *(const float2*)(gb + h*DHEAD + col);
                float y0 = yacc[mi][ni][hf*2+0], y1 = yacc[mi][ni][hf*2+1];
                float2 o;
                o.x = (y0 - mean)*rstd*w2.x + b2.x;
                o.y = (y1 - mean)*rstd*w2.y + b2.y;
                *(float2*)(dst + col) = o;
            }
        }
    }
}

// ---------------- launch ----------------------------------------------------
extern "C" void kernel_launch(void* const* d_in, const int* in_sizes, int n_in,
                              void* d_out, int out_size) {
    const float* X  = (const float*)d_in[0];
    const float* WQ = (const float*)d_in[1];
    const float* WK = (const float*)d_in[2];
    const float* WV = (const float*)d_in[3];
    const float* WG = (const float*)d_in[4];
    const float* WO = (const float*)d_in[5];
    const float* gw = (const float*)d_in[6];
    const float* gb = (const float*)d_in[7];
    float* out = (float*)d_out;

    cudaFuncSetAttribute(mm_kernel, cudaFuncAttributeMaxDynamicSharedMemorySize, MM_SMEM);
    cudaFuncSetAttribute(attn_kernel, cudaFuncAttributeMaxDynamicSharedMemorySize, ATT_SMEM);

    // merged tables + X rounding
    prep_kernel<<<(MROWS*DMODEL/8)/256, 256>>>(X);
    wtrans_kernel<<<dim3(32, 160), dim3(32, 8)>>>(WQ, WK, WV, WG, WO);

    // QKV projection + rotary + V transpose
    mm_kernel<<<dim3(24, 64), 256, MM_SMEM>>>(nullptr, 0, 0);

    // retention attention + fused group norm (2 CTA/SM, decay-windowed)
    attn_kernel<<<dim3(16, NHEADS, BATCH), 256, ATT_SMEM>>>(gw, gb);

    // gate GEMM + silu*Yn
    mm_kernel<<<dim3(8, 64), 256, MM_SMEM>>>(nullptr, 1, 3072);

    // output GEMM
    mm_kernel<<<dim3(8, 64), 256, MM_SMEM>>>(out, 2, 4096);
}

// round 16
// speedup vs baseline: 1.0240x; 1.0174x over previous
#include <cuda_runtime.h>
#include <cuda_fp16.h>
#include <math.h>
#include <stdint.h>

#define BATCH 4
#define LSEQ 2048
#define DMODEL 1024
#define NHEADS 8
#define DHEAD 128
#define MROWS (BATCH*LSEQ)

// ---------------- device scratch --------------------------------------------
__device__ __half g_Wt[5120*1024];                // transposed weights [n][k] fp16
__device__ __half g_Xr[MROWS*DMODEL];             // fp16 X
__device__ __half g_Q [BATCH*NHEADS*LSEQ*DHEAD];  // [b,h,l,e]
__device__ __half g_K [BATCH*NHEADS*LSEQ*DHEAD];
__device__ __half g_Vt[BATCH*NHEADS*DHEAD*LSEQ];  // [b,h,v,l]
__device__ float  g_G [MROWS*DMODEL];             // raw gate GEMM output f32
__device__ __half g_Sx[MROWS*DMODEL];             // silu(G)*Yn fp16
__device__ float g_qc[LSEQ*64];
__device__ float g_qs[LSEQ*64];
__device__ float g_kc[LSEQ*64];
__device__ float g_ks[LSEQ*64];
__device__ float g_pn[NHEADS*LSEQ];               // gamma^l
__device__ float g_pm[NHEADS*LSEQ];               // gamma^-l
__device__ int   g_win[NHEADS];                   // decay window (elements)

// ---------------- helpers ----------------------------------------------------
__device__ __forceinline__ uint32_t smem_u32(const void* p) {
    uint32_t a;
    asm("{ .reg .u64 t; cvta.to.shared.u64 t, %1; cvt.u32.u64 %0, t; }" : "=r"(a) : "l"(p));
    return a;
}
__device__ __forceinline__ void mma16(float d[4], uint32_t a0, uint32_t a1, uint32_t a2, uint32_t a3,
                                      uint32_t b0, uint32_t b1) {
    asm volatile(
        "mma.sync.aligned.m16n8k16.row.col.f32.f16.f16.f32 "
        "{%0,%1,%2,%3}, {%4,%5,%6,%7}, {%8,%9}, {%0,%1,%2,%3};"
        : "+f"(d[0]), "+f"(d[1]), "+f"(d[2]), "+f"(d[3])
        : "r"(a0), "r"(a1), "r"(a2), "r"(a3), "r"(b0), "r"(b1));
}
#define LDU(p) (*(const uint32_t*)(p))
#define CP16(dst, src)  asm volatile("cp.async.cg.shared.global [%0], [%1], 16;" :: "r"(dst), "l"(src) : "memory")
#define CPCOMMIT()      asm volatile("cp.async.commit_group;" ::: "memory")
#define CPWAIT0()       asm volatile("cp.async.wait_group 0;" ::: "memory")
#define CPWAIT1()       asm volatile("cp.async.wait_group 1;" ::: "memory")

// ---------------- merged prep: tables + X->fp16 ------------------------------
__global__ void prep_kernel(const float* __restrict__ X) {
    int idx = blockIdx.x*blockDim.x + threadIdx.x;
    {
        float4 v0 = ((const float4*)X)[idx*2];
        float4 v1 = ((const float4*)X)[idx*2 + 1];
        __half2 h[4];
        h[0] = __floats2half2_rn(v0.x, v0.y);
        h[1] = __floats2half2_rn(v0.z, v0.w);
        h[2] = __floats2half2_rn(v1.x, v1.y);
        h[3] = __floats2half2_rn(v1.z, v1.w);
        *(uint4*)(g_Xr + (size_t)idx*8) = *(uint4*)h;
    }
    if (idx < LSEQ*64) {
        int l = idx >> 6, j = idx & 63;
        float dh = (float)DHEAD;
        float base = (2.f*(float)j + 0.4f*dh) / (1.4f*dh);
        float scale = powf(base, (float)l / 512.0f);
        float inv_freq = powf(10000.0f, -(float)j / 64.0f);
        float arg = (float)l * inv_freq;
        float sv = sinf(arg), cv = cosf(arg);
        g_qc[idx] = cv * scale;
        g_qs[idx] = sv * scale;
        float iscale = 1.0f / scale;
        g_kc[idx] = cv * iscale;
        g_ks[idx] = sv * iscale;
    }
    if (idx < NHEADS*LSEQ) {
        int h = idx >> 11, k = idx & (LSEQ-1);
        float lg0 = logf(1.0f/32.0f), lg1 = logf(1.0f/512.0f);
        float lg = lg0 + (lg1 - lg0) * ((float)h / (float)(NHEADS-1));
        float gamma = 1.0f - expf(lg);
        double lng = (double)logf(gamma);
        g_pn[idx] = (float)exp((double)k * lng);
        g_pm[idx] = (float)exp(-(double)k * lng);
        if (k == 0) {
            double W = 11.512925 / (-lng);
            g_win[h] = (W >= 2047.0) ? 2047 : (int)W;
        }
    }
}

// ---------------- weight transpose -> fp16 ----------------------------------
__global__ void wtrans_kernel(const float* __restrict__ WQ, const float* __restrict__ WK,
                              const float* __restrict__ WV, const float* __restrict__ WG,
                              const float* __restrict__ WO) {
    __shared__ float t[32][33];
    int kT = blockIdx.x << 5, nT = blockIdx.y << 5;
    int tx = threadIdx.x, ty = threadIdx.y;   // 32 x 8
    #pragma unroll
    for (int r = 0; r < 4; r++) {
        int n = nT + tx, k = kT + ty + 8*r;
        float v;
        if (n < 3072) {
            int sel = n >> 10, h = (n >> 7) & 7, e = n & 127;
            const float* W = (sel == 0) ? WQ : (sel == 1) ? WK : WV;
            v = W[(size_t)h*131072 + (size_t)k*128 + e];
        } else if (n < 4096) {
            v = WG[(size_t)k*1024 + (n - 3072)];
        } else {
            v = WO[(size_t)k*1024 + (n - 4096)];
        }
        t[ty + 8*r][tx] = v;
    }
    __syncthreads();
    #pragma unroll
    for (int r = 0; r < 4; r++) {
        int n = nT + ty + 8*r, k = kT + tx;
        g_Wt[(size_t)n*1024 + k] = __float2half(t[tx][ty + 8*r]);
    }
}

// ---------------- unified fp16 mma GEMM: 3-stage, 1 barrier/chunk ------------
// mode 0: grid (32,64): x<24 -> QKV (rotary/V-transpose), x>=24 -> raw G f32
// mode 2: Sx @ WO -> Cout
#define MM_SMEM (110592)
__global__ __launch_bounds__(256) void mm_kernel(float* __restrict__ Cout, int mode, int wRowOff) {
    extern __shared__ __half smh[];
    const int tid = threadIdx.x;
    const int wid = tid >> 5, lane = tid & 31;
    const int q = lane >> 2, tq = lane & 3;
    const int wm = wid & 3, wn = wid >> 2;
    const int rb = blockIdx.y << 7, cb = blockIdx.x << 7;

    const __half* Ap = ((mode == 2) ? g_Sx : g_Xr) + (size_t)rb * 1024;
    const __half* Bp = g_Wt + (size_t)(wRowOff + cb) * 1024;

    uint32_t smb = smem_u32(smh);
    auto issue_chunk = [&](int kc, int s) {
        int kt = kc * 64;
        uint32_t ab = smb + (uint32_t)s * 18432u;
        uint32_t bb = smb + 55296u + (uint32_t)s * 18432u;
        #pragma unroll
        for (int i = 0; i < 4; i++) {
            int ch = tid + (i << 8);
            int r = ch >> 3, c8 = (ch & 7) << 3;
            CP16(ab + (uint32_t)(r*72 + c8)*2u, Ap + (size_t)r*1024 + kt + c8);
            CP16(bb + (uint32_t)(r*72 + c8)*2u, Bp + (size_t)r*1024 + kt + c8);
        }
        CPCOMMIT();
    };

    float acc[2][8][4];
    #pragma unroll
    for (int mi = 0; mi < 2; mi++)
        #pragma unroll
        for (int ni = 0; ni < 8; ni++)
            #pragma unroll
            for (int c = 0; c < 4; c++) acc[mi][ni][c] = 0.0f;

    issue_chunk(0, 0);
    issue_chunk(1, 1);

    #pragma unroll 1
    for (int k = 0; k < 16; k++) {
        int s = k % 3;
        if (k + 2 < 16) CPWAIT1(); else CPWAIT0();
        __syncthreads();
        if (k + 2 < 16) issue_chunk(k + 2, (k + 2) % 3);

        const __half* A_ = smh + s * 9216;
        const __half* B_ = smh + 27648 + s * 9216;
        #pragma unroll
        for (int ks = 0; ks < 4; ks++) {
            int c = ks*16 + 2*tq;
            uint32_t af[2][4];
            uint32_t bf[8][2];
            #pragma unroll
            for (int mi = 0; mi < 2; mi++) {
                int r = wm*32 + mi*16 + q;
                af[mi][0] = LDU(A_ + r*72 + c);
                af[mi][1] = LDU(A_ + (r+8)*72 + c);
                af[mi][2] = LDU(A_ + r*72 + c + 8);
                af[mi][3] = LDU(A_ + (r+8)*72 + c + 8);
            }
            #pragma unroll
            for (int ni = 0; ni < 8; ni++) {
                int n = wn*64 + ni*8 + q;
                bf[ni][0] = LDU(B_ + n*72 + c);
                bf[ni][1] = LDU(B_ + n*72 + c + 8);
            }
            #pragma unroll
            for (int ni = 0; ni < 8; ni++) {
                mma16(acc[0][ni], af[0][0], af[0][1], af[0][2], af[0][3], bf[ni][0], bf[ni][1]);
                mma16(acc[1][ni], af[1][0], af[1][1], af[1][2], af[1][3], bf[ni][0], bf[ni][1]);
            }
        }
    }

    // ---------------- epilogue ----------------
    int sel = 0, hh = 0;
    if (mode == 0) { sel = blockIdx.x >> 3; hh = blockIdx.x & 7; }

    #pragma unroll
    for (int mi = 0; mi < 2; mi++) {
        #pragma unroll
        for (int half_ = 0; half_ < 2; half_++) {
            int row = rb + wm*32 + mi*16 + q + half_*8;
            int bb = row >> 11, l = row & (LSEQ - 1);
            #pragma unroll
            for (int ni = 0; ni < 8; ni++) {
                int colb = wn*64 + ni*8 + 2*tq;
                float x1 = acc[mi][ni][half_*2 + 0];
                float x2 = acc[mi][ni][half_*2 + 1];
                if (mode == 0) {
                    size_t hbase = (size_t)(bb*NHEADS + hh);
                    if (sel == 3) {
                        // gate: raw f32 G
                        size_t off = (size_t)row*1024 + (cb - 3072) + colb;
                        *(float2*)(g_G + off) = make_float2(x1, x2);
                    } else if (sel == 2) {
                        __half* vt = g_Vt + hbase * (size_t)(DHEAD*LSEQ);
                        vt[(size_t)colb * LSEQ + l]       = __float2half(x1);
                        vt[(size_t)(colb + 1) * LSEQ + l] = __float2half(x2);
                    } else {
                        const float* ct = (sel == 0) ? g_qc : g_kc;
                        const float* st = (sel == 0) ? g_qs : g_ks;
                        int jj = colb >> 1;
                        float cv = ct[l*64 + jj], sv = st[l*64 + jj];
                        __half2 o = __floats2half2_rn(x1*cv - x2*sv, x2*cv + x1*sv);
                        __half* dst = ((sel == 0) ? g_Q : g_K) + (hbase*LSEQ + l)*DHEAD + colb;
                        *(__half2*)dst = o;
                    }
                } else {
                    size_t off = (size_t)row*1024 + cb + colb;
                    *(float2*)(Cout + off) = make_float2(x1, x2);
                }
            }
        }
    }
}

// ---------------- attention + fused groupnorm + gate -------------------------
// 104 KB smem -> 2 CTA/SM. Decay-window truncation per head.
// Epilogue: Yn = gn(Y)*gw+gb ; Sx = silu(G)*Yn -> fp16
#define QS_O  0
#define KS0_O 17408
#define KS1_O 26112
#define VS_O  34816
#define SS_O  44032
#define ATT_SMEM (53248*2)
__global__ __launch_bounds__(256, 2) void attn_kernel(
    const float* __restrict__ gw, const float* __restrict__ gb)
{
    extern __shared__ __half smh[];
    __half* Qs = smh + QS_O;
    __half* Ks[2] = { smh + KS0_O, smh + KS1_O };
    __half* Vs = smh + VS_O;
    __half* Ss = smh + SS_O;
    uint32_t smb = smem_u32(smh);
    uint32_t qsb = smb + QS_O*2u;
    uint32_t ksb[2] = { smb + KS0_O*2u, smb + KS1_O*2u };
    uint32_t vsb = smb + VS_O*2u;

    const int tid = threadIdx.x;
    const int wid = tid >> 5, lane = tid & 31;
    const int q = lane >> 2, tq = lane & 3;
    const int wm = wid & 3, wn = wid >> 2;

    int nt = (int)(gridDim.x - 1) - (int)blockIdx.x;   // big tiles first
    int h = blockIdx.y, b = blockIdx.z;
    int nb = nt << 7;

    size_t hb = (size_t)(b*NHEADS + h);
    const __half* Qg = g_Q + hb * (size_t)(LSEQ*DHEAD);
    const __half* Kg = g_K + hb * (size_t)(LSEQ*DHEAD);
    const __half* Vg = g_Vt + hb * (size_t)(DHEAD*LSEQ);
    const float* pm = g_pm + h*LSEQ;

    int nMt = 2*nt + 2;
    int mt0 = (nb - g_win[h]) >> 6;
    if (mt0 < 0) mt0 = 0;

    float pn[2][2];
    #pragma unroll
    for (int mi = 0; mi < 2; mi++)
        #pragma unroll
        for (int hf = 0; hf < 2; hf++)
            pn[mi][hf] = g_pn[h*LSEQ + nb + wm*32 + mi*16 + q + hf*8];

    // prologue: Q + K[mt0], one commit group
    {
        int r = tid >> 1, part = (tid & 1) * 64;
        const __half* src = Qg + (size_t)(nb + r)*DHEAD + part;
        #pragma unroll
        for (int i = 0; i < 8; i++)
            CP16(qsb + (uint32_t)(r*136 + part + i*8)*2u, src + i*8);
        int kr = tid >> 2, kc = (tid & 3) * 32;
        const __half* ksrc = Kg + (size_t)(mt0*64 + kr)*DHEAD + kc;
        #pragma unroll
        for (int i = 0; i < 4; i++)
            CP16(ksb[0] + (uint32_t)(kr*136 + kc + i*8)*2u, ksrc + i*8);
        CPCOMMIT();
    }

    float yacc[2][8][4];
    #pragma unroll
    for (int mi = 0; mi < 2; mi++)
        #pragma unroll
        for (int ni = 0; ni < 8; ni++)
            #pragma unroll
            for (int c = 0; c < 4; c++) yacc[mi][ni][c] = 0.0f;

    #pragma unroll 1
    for (int mt = mt0; mt < nMt; mt++) {
        int mb_ = mt << 6;
        int buf = (mt - mt0) & 1;
        CPWAIT0();
        __syncthreads();

        {
            int vr = tid >> 1, vc = (tid & 1) * 32;
            const __half* vsrc = Vg + (size_t)vr*LSEQ + mb_ + vc;
            #pragma unroll
            for (int i = 0; i < 4; i++)
                CP16(vsb + (uint32_t)(vr*72 + vc + i*8)*2u, vsrc + i*8);
            CPCOMMIT();
        }
        if (mt + 1 < nMt) {
            int kr = tid >> 2, kc = (tid & 3) * 32;
            const __half* ksrc = Kg + (size_t)(mb_ + 64 + kr)*DHEAD + kc;
            #pragma unroll
            for (int i = 0; i < 4; i++)
                CP16(ksb[buf^1] + (uint32_t)(kr*136 + kc + i*8)*2u, ksrc + i*8);
            CPCOMMIT();
        }

        const __half* K_ = Ks[buf];
        float sacc[2][4][4];
        #pragma unroll
        for (int mi = 0; mi < 2; mi++)
            #pragma unroll
            for (int ni = 0; ni < 4; ni++)
                #pragma unroll
                for (int c = 0; c < 4; c++) sacc[mi][ni][c] = 0.0f;
        #pragma unroll
        for (int ks = 0; ks < 8; ks++) {
            int c = ks*16 + 2*tq;
            uint32_t af[2][4];
            uint32_t bf[4][2];
            #pragma unroll
            for (int mi = 0; mi < 2; mi++) {
                int r = wm*32 + mi*16 + q;
                af[mi][0] = LDU(Qs + r*136 + c);
                af[mi][1] = LDU(Qs + (r+8)*136 + c);
                af[mi][2] = LDU(Qs + r*136 + c + 8);
                af[mi][3] = LDU(Qs + (r+8)*136 + c + 8);
            }
            #pragma unroll
            for (int ni = 0; ni < 4; ni++) {
                int m = wn*32 + ni*8 + q;
                bf[ni][0] = LDU(K_ + m*136 + c);
                bf[ni][1] = LDU(K_ + m*136 + c + 8);
            }
            #pragma unroll
            for (int ni = 0; ni < 4; ni++) {
                mma16(sacc[0][ni], af[0][0], af[0][1], af[0][2], af[0][3], bf[ni][0], bf[ni][1]);
                mma16(sacc[1][ni], af[1][0], af[1][1], af[1][2], af[1][3], bf[ni][0], bf[ni][1]);
            }
        }

        #pragma unroll
        for (int mi = 0; mi < 2; mi++) {
            #pragma unroll
            for (int hf = 0; hf < 2; hf++) {
                int r = wm*32 + mi*16 + q + hf*8;
                int n_ = nb + r;
                float pnv = pn[mi][hf];
                #pragma unroll
                for (int ni = 0; ni < 4; ni++) {
                    int m = wn*32 + ni*8 + 2*tq;
                    int mg = mb_ + m;
                    float2 ip = *(const float2*)(pm + mg);
                    float v0 = (n_ >= mg) ? sacc[mi][ni][hf*2+0] * (pnv*ip.x) : 0.0f;
                    float v1 = (n_ >  mg) ? sacc[mi][ni][hf*2+1] * (pnv*ip.y) : 0.0f;
                    *(__half2*)(Ss + r*72 + m) = __floats2half2_rn(v0, v1);
                }
            }
        }
        if (mt + 1 < nMt) CPWAIT1(); else CPWAIT0();
        __syncthreads();

        #pragma unroll
        for (int ks = 0; ks < 4; ks++) {
            int c = ks*16 + 2*tq;
            uint32_t af[2][4];
            uint32_t bf[8][2];
            #pragma unroll
            for (int mi = 0; mi < 2; mi++) {
                int r = wm*32 + mi*16 + q;
                af[mi][0] = LDU(Ss + r*72 + c);
                af[mi][1] = LDU(Ss + (r+8)*72 + c);
                af[mi][2] = LDU(Ss + r*72 + c + 8);
                af[mi][3] = LDU(Ss + (r+8)*72 + c + 8);
            }
            #pragma unroll
            for (int ni = 0; ni < 8; ni++) {
                int v = wn*64 + ni*8 + q;
                bf[ni][0] = LDU(Vs + v*72 + c);
                bf[ni][1] = LDU(Vs + v*72 + c + 8);
            }
            #pragma unroll
            for (int ni = 0; ni < 8; ni++) {
                mma16(yacc[0][ni], af[0][0], af[0][1], af[0][2], af[0][3], bf[ni][0], bf[ni][1]);
                mma16(yacc[1][ni], af[1][0], af[1][1], af[1][2], af[1][3], bf[ni][0], bf[ni][1]);
            }
        }
    }

    // -------- fused group norm + gate: Sx = silu(G) * (gn(Y)*gw+gb) ----------
    __syncthreads();
    float* fb = (float*)smh;
    #pragma unroll
    for (int mi = 0; mi < 2; mi++) {
        #pragma unroll
        for (int hf = 0; hf < 2; hf++) {
            int row = wm*32 + mi*16 + hf*8 + q;
            float s = 0.0f, ss = 0.0f;
            #pragma unroll
            for (int ni = 0; ni < 8; ni++) {
                float a = yacc[mi][ni][hf*2+0], b2 = yacc[mi][ni][hf*2+1];
                s += a + b2; ss += a*a + b2*b2;
            }
            s  += __shfl_xor_sync(0xffffffffu, s, 1);
            ss += __shfl_xor_sync(0xffffffffu, ss, 1);
            s  += __shfl_xor_sync(0xffffffffu, s, 2);
            ss += __shfl_xor_sync(0xffffffffu, ss, 2);
            if (tq == 0) { fb[row*4 + wn*2] = s; fb[row*4 + wn*2 + 1] = ss; }
        }
    }
    __syncthreads();
    #pragma unroll
    for (int mi = 0; mi < 2; mi++) {
        #pragma unroll
        for (int hf = 0; hf < 2; hf++) {
            int row = wm*32 + mi*16 + hf*8 + q;
            float s  = fb[row*4 + 0] + fb[row*4 + 2];
            float ss = fb[row*4 + 1] + fb[row*4 + 3];
            float mean = s * (1.0f/DHEAD);
            float var  = ss * (1.0f/DHEAD) - mean*mean;
            float rstd = rsqrtf(var + 1e-5f);
            int l = nb + row;
            size_t rowoff = ((size_t)(b*LSEQ + l))*DMODEL + h*DHEAD;
            const float* gsrc = g_G + rowoff;
            __half* dst = g_Sx + rowoff;
            #pragma unroll
            for (int ni = 0; ni < 8; ni++) {
                int col = wn*64 + ni*8 + 2*tq;
                float2 w2 = *(const float2*)(gw + h*DHEAD + col);
                float2 b2 = *(const float2*)(gb + h*DHEAD + col);
                float2 g2 = *(const float2*)(gsrc + col);
                float y0 = yacc[mi][ni][hf*2+0], y1 = yacc[mi][ni][hf*2+1];
                float yn0 = (y0 - mean)*rstd*w2.x + b2.x;
                float yn1 = (y1 - mean)*rstd*w2.y + b2.y;
                float s0 = (g2.x / (1.0f + expf(-g2.x))) * yn0;
                float s1 = (g2.y / (1.0f + expf(-g2.y))) * yn1;
                *(__half2*)(dst + col) = __floats2half2_rn(s0, s1);
            }
        }
    }
}

// ---------------- launch ----------------------------------------------------
extern "C" void kernel_launch(void* const* d_in, const int* in_sizes, int n_in,
                              void* d_out, int out_size) {
    const float* X  = (const float*)d_in[0];
    const float* WQ = (const float*)d_in[1];
    const float* WK = (const float*)d_in[2];
    const float* WV = (const float*)d_in[3];
    const float* WG = (const float*)d_in[4];
    const float* WO = (const float*)d_in[5];
    const float* gw = (const float*)d_in[6];
    const float* gb = (const float*)d_in[7];
    float* out = (float*)d_out;

    cudaFuncSetAttribute(mm_kernel, cudaFuncAttributeMaxDynamicSharedMemorySize, MM_SMEM);
    cudaFuncSetAttribute(attn_kernel, cudaFuncAttributeMaxDynamicSharedMemorySize, ATT_SMEM);

    // merged tables + X rounding
    prep_kernel<<<(MROWS*DMODEL/8)/256, 256>>>(X);
    wtrans_kernel<<<dim3(32, 160), dim3(32, 8)>>>(WQ, WK, WV, WG, WO);

    // QKV + gate projections (rotary, V transpose, raw G)
    mm_kernel<<<dim3(32, 64), 256, MM_SMEM>>>(nullptr, 0, 0);

    // retention attention + fused group norm + silu(G) gate -> Sx fp16
    attn_kernel<<<dim3(16, NHEADS, BATCH), 256, ATT_SMEM>>>(gw, gb);

    // output GEMM
    mm_kernel<<<dim3(8, 64), 256, MM_SMEM>>>(out, 2, 4096);
}